// round 1
// baseline (speedup 1.0000x reference)
#include <cuda_runtime.h>
#include <cuda_bf16.h>

#define TT 32   // tokens per node (M+1)
#define MMSG 31
#define EE 64
#define AA 64
#define SELF_REL 200

__global__ __launch_bounds__(256, 4) void transpool_kernel(
    const float* __restrict__ h,
    const float* __restrict__ msg,
    const int*   __restrict__ msg_type,
    const int*   __restrict__ r_label_node,
    const int*   __restrict__ r_label_msg,
    const float* __restrict__ W_self,
    const float* __restrict__ Q,
    const float* __restrict__ K,
    const float* __restrict__ V,
    const float* __restrict__ ffn_w,
    const float* __restrict__ ffn_b,
    float* __restrict__ out)
{
    const int n   = blockIdx.x;
    const int tid = threadIdx.x;
    const int w   = tid >> 5;
    const int l   = tid & 31;

    __shared__ float xs[TT][EE + 1];
    __shared__ float qs[TT][EE + 1];
    __shared__ float ks[TT][EE + 1];
    __shared__ float vs[TT][EE + 1];
    __shared__ float sc[TT][TT + 1];
    __shared__ float hrow[EE];
    __shared__ float att0[TT];
    __shared__ float pooled[AA];

    // ---- Stage x = [h@W_self ; msg] into SMEM -----------------------------
    if (tid < EE) hrow[tid] = h[n * EE + tid];
    for (int i = tid; i < MMSG * EE; i += 256) {
        int mrow = i / EE, e = i - mrow * EE;
        xs[1 + mrow][e] = msg[(size_t)n * MMSG * EE + i];
    }
    __syncthreads();
    if (tid < EE) {
        float acc = 0.f;
        #pragma unroll
        for (int e = 0; e < EE; e++) acc = fmaf(hrow[e], W_self[e * EE + tid], acc);
        xs[0][tid] = acc;
    }
    __syncthreads();

    // ---- Per-token relation-gathered projections (the hot loop) -----------
    // warp w handles tokens m = w, w+8, w+16, w+24; lane produces 2 outputs
    // per matrix via float2 loads (fully coalesced 256B rows from L2).
    #pragma unroll
    for (int it = 0; it < 4; it++) {
        const int m = w + it * 8;
        const int midx = n * MMSG + m - 1;
        const int rqv = (m == 0) ? r_label_node[n] : r_label_msg[midx];
        const int rk  = (m == 0) ? SELF_REL        : msg_type[midx];
        const float2* __restrict__ Qr = (const float2*)(Q + (size_t)rqv * EE * AA);
        const float2* __restrict__ Kr = (const float2*)(K + (size_t)rk  * EE * AA);
        const float2* __restrict__ Vr = (const float2*)(V + (size_t)rqv * EE * AA);
        float q0 = 0.f, q1 = 0.f, k0 = 0.f, k1 = 0.f, v0 = 0.f, v1 = 0.f;
        #pragma unroll
        for (int e = 0; e < EE; e++) {
            const float xe = xs[m][e];            // warp broadcast
            const float2 wq = Qr[e * 32 + l];
            const float2 wk = Kr[e * 32 + l];
            const float2 wv = Vr[e * 32 + l];
            q0 = fmaf(xe, wq.x, q0); q1 = fmaf(xe, wq.y, q1);
            k0 = fmaf(xe, wk.x, k0); k1 = fmaf(xe, wk.y, k1);
            v0 = fmaf(xe, wv.x, v0); v1 = fmaf(xe, wv.y, v1);
        }
        qs[m][2 * l] = q0; qs[m][2 * l + 1] = q1;
        ks[m][2 * l] = k0; ks[m][2 * l + 1] = k1;
        vs[m][2 * l] = v0; vs[m][2 * l + 1] = v1;
    }
    __syncthreads();

    // ---- scores[q][k] = (q_vec . k_vec) / sqrt(64) -------------------------
    #pragma unroll
    for (int idx = tid; idx < TT * TT; idx += 256) {
        const int qr = idx >> 5, kc = idx & 31;
        float acc = 0.f;
        #pragma unroll
        for (int e = 0; e < EE; e++) acc = fmaf(qs[qr][e], ks[kc][e], acc);
        sc[qr][kc] = acc * 0.125f;
    }
    __syncthreads();

    // ---- softmax over the QUERY axis (per k-column); only row 0 needed ----
    if (tid < TT) {
        const int kc = tid;
        float mx = -1e30f;
        #pragma unroll
        for (int q = 0; q < TT; q++) mx = fmaxf(mx, sc[q][kc]);
        float s = 0.f;
        #pragma unroll
        for (int q = 0; q < TT; q++) s += __expf(sc[q][kc] - mx);
        att0[kc] = __expf(sc[0][kc] - mx) / s;
    }
    __syncthreads();

    // ---- pooled[a] = sum_k att0[k] * v[k][a] --------------------------------
    if (tid < AA) {
        float acc = 0.f;
        #pragma unroll
        for (int k = 0; k < TT; k++) acc = fmaf(att0[k], vs[k][tid], acc);
        pooled[tid] = acc;
    }
    __syncthreads();

    // ---- out = pooled @ ffn_w + ffn_b ---------------------------------------
    if (tid < EE) {
        float acc = ffn_b[tid];
        #pragma unroll
        for (int a = 0; a < AA; a++) acc = fmaf(pooled[a], ffn_w[a * EE + tid], acc);
        out[n * EE + tid] = acc;
    }
}

extern "C" void kernel_launch(void* const* d_in, const int* in_sizes, int n_in,
                              void* d_out, int out_size) {
    const float* h            = (const float*)d_in[0];
    const float* msg          = (const float*)d_in[1];
    const int*   msg_type     = (const int*)  d_in[2];
    const int*   r_label_node = (const int*)  d_in[3];
    const int*   r_label_msg  = (const int*)  d_in[4];
    const float* W_self       = (const float*)d_in[5];
    const float* Q            = (const float*)d_in[6];
    const float* K            = (const float*)d_in[7];
    const float* V            = (const float*)d_in[8];
    const float* ffn_w        = (const float*)d_in[9];
    const float* ffn_b        = (const float*)d_in[10];
    float* out = (float*)d_out;

    const int N = in_sizes[0] / EE;   // 512
    transpool_kernel<<<N, 256>>>(h, msg, msg_type, r_label_node, r_label_msg,
                                 W_self, Q, K, V, ffn_w, ffn_b, out);
}